// round 2
// baseline (speedup 1.0000x reference)
#include <cuda_runtime.h>

// Problem constants
#define HW 262144        // 512*512
#define NB 8
#define CH 10
// Folded-parameter layout (floats):
//   [0,640)    W1t  : hf layer1, [c][o] c-major, entry = w_hf1[o][c]*scale1[o]
//   [640,1280) W3t  : up layer1, same layout
//   [1280,1664) W2f : hf layer2, [o][c] padded to 12, entry = w_hf2[c][o]*scale2[c]
//   [1664,2048) W4f : up layer2, same
//   [2048,2080) B1  ; [2080,2112) B3 ; [2112,2124) B2 ; [2124,2136) B4
#define FOLD_FLOATS 2136

__device__ float g_fold[FOLD_FLOATS];

// ---------------------------------------------------------------------------
// Packed fp32x2 FMA (Blackwell): d = a*b + c elementwise on both halves.
// ptxas resolves the mov.b64 pack/unpack into register-pair allocation.
// ---------------------------------------------------------------------------
__device__ __forceinline__ float2 ffma2(float2 a, float2 b, float2 c) {
    float2 d;
    asm("{\n\t"
        ".reg .b64 ra, rb, rc;\n\t"
        "mov.b64 ra, {%2, %3};\n\t"
        "mov.b64 rb, {%4, %5};\n\t"
        "mov.b64 rc, {%6, %7};\n\t"
        "fma.rn.f32x2 rc, ra, rb, rc;\n\t"
        "mov.b64 {%0, %1}, rc;\n\t"
        "}"
        : "=f"(d.x), "=f"(d.y)
        : "f"(a.x), "f"(a.y), "f"(b.x), "f"(b.y), "f"(c.x), "f"(c.y));
    return d;
}

// ---------------------------------------------------------------------------
// Prep kernel: fold BN (inference) into conv weights/biases once per launch.
// scale = g * rsqrt(v + 1e-5); shift = b - m*scale
// ---------------------------------------------------------------------------
__global__ void fold_kernel(
    const float* __restrict__ w1, const float* __restrict__ g1, const float* __restrict__ b1,
    const float* __restrict__ m1, const float* __restrict__ v1,
    const float* __restrict__ w2, const float* __restrict__ g2, const float* __restrict__ b2,
    const float* __restrict__ m2, const float* __restrict__ v2,
    const float* __restrict__ w3, const float* __restrict__ g3, const float* __restrict__ b3,
    const float* __restrict__ m3, const float* __restrict__ v3,
    const float* __restrict__ w4, const float* __restrict__ g4, const float* __restrict__ b4,
    const float* __restrict__ m4, const float* __restrict__ v4)
{
    int i = threadIdx.x;
    for (int idx = i; idx < 640; idx += blockDim.x) {       // W1t [c][o]
        int c = idx >> 5, o = idx & 31;
        float s = g1[o] * rsqrtf(v1[o] + 1e-5f);
        g_fold[idx] = w1[o * 20 + c] * s;
    }
    for (int idx = i; idx < 640; idx += blockDim.x) {       // W3t
        int c = idx >> 5, o = idx & 31;
        float s = g3[o] * rsqrtf(v3[o] + 1e-5f);
        g_fold[640 + idx] = w3[o * 20 + c] * s;
    }
    for (int idx = i; idx < 384; idx += blockDim.x) {       // W2f [o][c pad 12]
        int o = idx / 12, c = idx % 12;
        float val = 0.f;
        if (c < 10) { float s = g2[c] * rsqrtf(v2[c] + 1e-5f); val = w2[c * 32 + o] * s; }
        g_fold[1280 + idx] = val;
    }
    for (int idx = i; idx < 384; idx += blockDim.x) {       // W4f
        int o = idx / 12, c = idx % 12;
        float val = 0.f;
        if (c < 10) { float s = g4[c] * rsqrtf(v4[c] + 1e-5f); val = w4[c * 32 + o] * s; }
        g_fold[1664 + idx] = val;
    }
    if (i < 32) {
        float s = g1[i] * rsqrtf(v1[i] + 1e-5f);
        g_fold[2048 + i] = b1[i] - m1[i] * s;
    } else if (i < 64) {
        int o = i - 32;
        float s = g3[o] * rsqrtf(v3[o] + 1e-5f);
        g_fold[2080 + o] = b3[o] - m3[o] * s;
    } else if (i < 76) {
        int c = i - 64;
        float val = 0.f;
        if (c < 10) { float s = g2[c] * rsqrtf(v2[c] + 1e-5f); val = b2[c] - m2[c] * s; }
        g_fold[2112 + c] = val;
    } else if (i < 88) {
        int c = i - 76;
        float val = 0.f;
        if (c < 10) { float s = g4[c] * rsqrtf(v4[c] + 1e-5f); val = b4[c] - m4[c] * s; }
        g_fold[2124 + c] = val;
    }
}

// ---------------------------------------------------------------------------
// One block: y10 = relu(BN2(W2 @ relu(BN1(W1 @ x20))))  for 2 pixels.
// xb[p][c] holds x duplicated into both halves: (v,v).
// Stage A pairs output channels (weight pairs contiguous in SMEM row).
// Stage B pairs the 10 output channels (weight row contiguous), h broadcast.
// out2[cp][p] = channels (2cp, 2cp+1) of pixel p.
// ---------------------------------------------------------------------------
__device__ __forceinline__ void run_block(
    const float2 (&xb)[2][20],
    const float* __restrict__ sWt, const float* __restrict__ sBa,
    const float* __restrict__ sW2, const float* __restrict__ sBb,
    float2 (&out2)[5][2])
{
#pragma unroll
    for (int cp = 0; cp < 5; cp++) {
        float2 bb = *reinterpret_cast<const float2*>(sBb + 2 * cp);
        out2[cp][0] = bb; out2[cp][1] = bb;
    }
#pragma unroll
    for (int ob = 0; ob < 32; ob += 4) {
        float2 b01 = *reinterpret_cast<const float2*>(sBa + ob);
        float2 b23 = *reinterpret_cast<const float2*>(sBa + ob + 2);
        float2 a00 = b01, a01 = b01, a10 = b23, a11 = b23;
#pragma unroll
        for (int c = 0; c < 20; c++) {
            float4 w = *reinterpret_cast<const float4*>(sWt + c * 32 + ob);
            float2 w01 = make_float2(w.x, w.y);
            float2 w23 = make_float2(w.z, w.w);
            a00 = ffma2(w01, xb[0][c], a00);
            a01 = ffma2(w01, xb[1][c], a01);
            a10 = ffma2(w23, xb[0][c], a10);
            a11 = ffma2(w23, xb[1][c], a11);
        }
        a00.x = fmaxf(a00.x, 0.f); a00.y = fmaxf(a00.y, 0.f);
        a01.x = fmaxf(a01.x, 0.f); a01.y = fmaxf(a01.y, 0.f);
        a10.x = fmaxf(a10.x, 0.f); a10.y = fmaxf(a10.y, 0.f);
        a11.x = fmaxf(a11.x, 0.f); a11.y = fmaxf(a11.y, 0.f);
#pragma unroll
        for (int j = 0; j < 4; j++) {
            float h0 = (j == 0) ? a00.x : (j == 1) ? a00.y : (j == 2) ? a10.x : a10.y;
            float h1 = (j == 0) ? a01.x : (j == 1) ? a01.y : (j == 2) ? a11.x : a11.y;
            float2 hb0 = make_float2(h0, h0);
            float2 hb1 = make_float2(h1, h1);
            const float* r = sW2 + (ob + j) * 12;
            float4 wa = *reinterpret_cast<const float4*>(r);
            float4 wb = *reinterpret_cast<const float4*>(r + 4);
            float2 wc = *reinterpret_cast<const float2*>(r + 8);
            float2 w0 = make_float2(wa.x, wa.y);
            float2 w1 = make_float2(wa.z, wa.w);
            float2 w2 = make_float2(wb.x, wb.y);
            float2 w3 = make_float2(wb.z, wb.w);
            out2[0][0] = ffma2(w0, hb0, out2[0][0]); out2[0][1] = ffma2(w0, hb1, out2[0][1]);
            out2[1][0] = ffma2(w1, hb0, out2[1][0]); out2[1][1] = ffma2(w1, hb1, out2[1][1]);
            out2[2][0] = ffma2(w2, hb0, out2[2][0]); out2[2][1] = ffma2(w2, hb1, out2[2][1]);
            out2[3][0] = ffma2(w3, hb0, out2[3][0]); out2[3][1] = ffma2(w3, hb1, out2[3][1]);
            out2[4][0] = ffma2(wc, hb0, out2[4][0]); out2[4][1] = ffma2(wc, hb1, out2[4][1]);
        }
    }
#pragma unroll
    for (int cp = 0; cp < 5; cp++) {
        out2[cp][0].x = fmaxf(out2[cp][0].x, 0.f); out2[cp][0].y = fmaxf(out2[cp][0].y, 0.f);
        out2[cp][1].x = fmaxf(out2[cp][1].x, 0.f); out2[cp][1].y = fmaxf(out2[cp][1].y, 0.f);
    }
}

// ---------------------------------------------------------------------------
// Fully fused kernel: message + xf_new per pixel pair, message never re-read.
// ---------------------------------------------------------------------------
__global__ void __launch_bounds__(128) fused_kernel(
    const float* __restrict__ xf, const float* __restrict__ xh1,
    const float* __restrict__ xh2, float* __restrict__ out)
{
    __shared__ __align__(16) float sf[FOLD_FLOATS];
    {
        const float4* src = reinterpret_cast<const float4*>(g_fold);
        float4* dst = reinterpret_cast<float4*>(sf);
        for (int i = threadIdx.x; i < FOLD_FLOATS / 4; i += 128) dst[i] = src[i];
    }
    __syncthreads();
    const float* sW1t = sf;
    const float* sW3t = sf + 640;
    const float* sW2f = sf + 1280;
    const float* sW4f = sf + 1664;
    const float* sB1  = sf + 2048;
    const float* sB3  = sf + 2080;
    const float* sB2  = sf + 2112;
    const float* sB4  = sf + 2124;

    int t  = blockIdx.x * 128 + threadIdx.x;   // pixel-pair index
    int b  = t >> 17;                          // 131072 pairs per batch
    int hw = (t & 0x1FFFF) << 1;
    size_t base = (size_t)b * CH * HW + hw;
    const float* ph1 = xh1 + base;
    const float* ph2 = xh2 + base;
    const float* pf  = xf  + base;
    float* po_new = out + base;
    float* po_msg = out + (size_t)NB * CH * HW + base;

    float2 xb[2][20];
#pragma unroll
    for (int c = 0; c < 10; c++) {
        float2 v = *reinterpret_cast<const float2*>(ph1 + (size_t)c * HW);
        xb[0][c] = make_float2(v.x, v.x);
        xb[1][c] = make_float2(v.y, v.y);
    }
#pragma unroll
    for (int c = 0; c < 10; c++) {
        float2 v = *reinterpret_cast<const float2*>(ph2 + (size_t)c * HW);
        xb[0][10 + c] = make_float2(v.x, v.x);
        xb[1][10 + c] = make_float2(v.y, v.y);
    }

    float2 msg2[5][2];
    run_block(xb, sW1t, sB1, sW2f, sB2, msg2);

#pragma unroll
    for (int cp = 0; cp < 5; cp++) {
        float2 m0 = msg2[cp][0], m1 = msg2[cp][1];
        *reinterpret_cast<float2*>(po_msg + (size_t)(2 * cp)     * HW) = make_float2(m0.x, m1.x);
        *reinterpret_cast<float2*>(po_msg + (size_t)(2 * cp + 1) * HW) = make_float2(m0.y, m1.y);
        xb[0][10 + 2 * cp]     = make_float2(m0.x, m0.x);
        xb[0][10 + 2 * cp + 1] = make_float2(m0.y, m0.y);
        xb[1][10 + 2 * cp]     = make_float2(m1.x, m1.x);
        xb[1][10 + 2 * cp + 1] = make_float2(m1.y, m1.y);
    }
#pragma unroll
    for (int c = 0; c < 10; c++) {
        float2 v = *reinterpret_cast<const float2*>(pf + (size_t)c * HW);
        xb[0][c] = make_float2(v.x, v.x);
        xb[1][c] = make_float2(v.y, v.y);
    }

    float2 r2[5][2];
    run_block(xb, sW3t, sB3, sW4f, sB4, r2);

#pragma unroll
    for (int cp = 0; cp < 5; cp++) {
        float2 r0 = r2[cp][0], r1 = r2[cp][1];
        *reinterpret_cast<float2*>(po_new + (size_t)(2 * cp)     * HW) = make_float2(r0.x, r1.x);
        *reinterpret_cast<float2*>(po_new + (size_t)(2 * cp + 1) * HW) = make_float2(r0.y, r1.y);
    }
}

extern "C" void kernel_launch(void* const* d_in, const int* in_sizes, int n_in,
                              void* d_out, int out_size) {
    const float* xf  = (const float*)d_in[0];
    const float* xh1 = (const float*)d_in[1];
    const float* xh2 = (const float*)d_in[2];

    fold_kernel<<<1, 256>>>(
        (const float*)d_in[3],  (const float*)d_in[4],  (const float*)d_in[5],
        (const float*)d_in[6],  (const float*)d_in[7],
        (const float*)d_in[8],  (const float*)d_in[9],  (const float*)d_in[10],
        (const float*)d_in[11], (const float*)d_in[12],
        (const float*)d_in[13], (const float*)d_in[14], (const float*)d_in[15],
        (const float*)d_in[16], (const float*)d_in[17],
        (const float*)d_in[18], (const float*)d_in[19], (const float*)d_in[20],
        (const float*)d_in[21], (const float*)d_in[22]);

    // 8*512*512/2 = 1,048,576 pixel pairs; 128 threads/block -> 8192 blocks exact
    fused_kernel<<<8192, 128>>>(xf, xh1, xh2, (float*)d_out);
}